// round 16
// baseline (speedup 1.0000x reference)
#include <cuda_runtime.h>
#include <cstdint>

// Harmonic lattice potential — FINAL (= R13, measured best 59.87us).
//   inputs: pos (N,3) f32, edge_index (2,E) int32, batch (N,) i32 (sorted)
//   output: energy (64,) f32 ++ forces (N,3) f32
//
// Design (validated over 14 rounds):
//   - prep: pack pos->float4 + zero accumulators + zero energy slots (one
//     plain kernel; launch-ramp bound, ~4.3us — slimming/splitting/overlap
//     all regressed: R5, R14).
//   - edge: exact-fit grid, 4 edges/thread, int4 index loads, float4 pos
//     gathers, red.global.add.v4.f32 (force.xyz + energy in .w), rsqrt
//     math, 64-thread CTAs. At its L1tex random-wavefront floor
//     (~4.1 wf/edge ~ 48-51us). Grid-stride (R2/R7/R8), 8 edges/thread
//     (R6), PDL (R4), fusion (R7/R8) all regressed.
//   - finalize: coalesced force writes + smem energy binning by sorted
//     batch, 128t.

#define R0F 1.0f
#define NUM_GRAPHS 64
#define MAXN 131072

__device__ float4 g_acc[MAXN];    // force.xyz + energy.w accumulator
__device__ float4 g_pos4[MAXN];   // packed positions

__device__ __forceinline__ void red_add_v4(float4* addr, float a, float b, float c, float d) {
    asm volatile("red.global.add.v4.f32 [%0], {%1, %2, %3, %4};"
                 :: "l"(addr), "f"(a), "f"(b), "f"(c), "f"(d));
}

__global__ void prep_kernel(const float* __restrict__ pos, float* __restrict__ out, int N) {
    int t = blockIdx.x * blockDim.x + threadIdx.x;
    if (t < N) {
        g_acc[t]  = make_float4(0.f, 0.f, 0.f, 0.f);
        g_pos4[t] = make_float4(__ldg(&pos[3 * t]), __ldg(&pos[3 * t + 1]),
                                __ldg(&pos[3 * t + 2]), 0.f);
    }
    if (t < NUM_GRAPHS) out[t] = 0.f;   // zero energy slots (d_out poisoned)
}

// Vector path: E % 4 == 0. One quad (4 edges) per thread, exact grid, 64t CTAs.
__global__ void __launch_bounds__(64)
edge_vec_kernel(const int4* __restrict__ ia, const int4* __restrict__ ja, int Q) {
    int q = blockIdx.x * blockDim.x + threadIdx.x;
    if (q >= Q) return;

    int4 iv = __ldg(&ia[q]);
    int4 jv = __ldg(&ja[q]);
    int is[4] = {iv.x, iv.y, iv.z, iv.w};
    int js[4] = {jv.x, jv.y, jv.z, jv.w};

    float4 pi[4], pj[4];
#pragma unroll
    for (int k = 0; k < 4; k++) {
        pi[k] = __ldg(&g_pos4[is[k]]);
        pj[k] = __ldg(&g_pos4[js[k]]);
    }

#pragma unroll
    for (int k = 0; k < 4; k++) {
        float dx = pi[k].x - pj[k].x;
        float dy = pi[k].y - pj[k].y;
        float dz = pi[k].z - pj[k].z;
        float dd = fmaf(dx, dx, fmaf(dy, dy, dz * dz));
        float rinv = rsqrtf(fmaxf(dd, 1e-40f));
        float d = dd * rinv;                  // = sqrt(dd); 0 when dd==0
        float delta = d - R0F;                // K = 1
        float e = 0.5f * delta * delta;
        float s = delta * rinv;               // dx==0 when dd==0 -> force 0
        float fx = s * dx, fy = s * dy, fz = s * dz;

        red_add_v4(&g_acc[is[k]], -fx, -fy, -fz, e);
        red_add_v4(&g_acc[js[k]],  fx,  fy,  fz, 0.f);
    }
}

// Scalar fallback (E % 4 != 0 — not expected for this dataset).
__global__ void edge_scalar_kernel(const int* __restrict__ ei, int E) {
    int e = blockIdx.x * blockDim.x + threadIdx.x;
    if (e >= E) return;
    int i = __ldg(&ei[e]);
    int j = __ldg(&ei[E + e]);
    float4 pi = __ldg(&g_pos4[i]);
    float4 pj = __ldg(&g_pos4[j]);
    float dx = pi.x - pj.x, dy = pi.y - pj.y, dz = pi.z - pj.z;
    float dd = fmaf(dx, dx, fmaf(dy, dy, dz * dz));
    float rinv = rsqrtf(fmaxf(dd, 1e-40f));
    float d = dd * rinv;
    float delta = d - R0F;
    float e2 = 0.5f * delta * delta;
    float s = delta * rinv;
    float fx = s * dx, fy = s * dy, fz = s * dz;
    red_add_v4(&g_acc[i], -fx, -fy, -fz, e2);
    red_add_v4(&g_acc[j],  fx,  fy,  fz, 0.f);
}

__global__ void finalize_kernel(float* __restrict__ out,
                                const int* __restrict__ batch, int N) {
    __shared__ float ebins[NUM_GRAPHS];
    int t = threadIdx.x;
    if (t < NUM_GRAPHS) ebins[t] = 0.f;
    __syncthreads();

    int n = blockIdx.x * blockDim.x + t;
    if (n < N) {
        float4 a = g_acc[n];
        out[NUM_GRAPHS + 3 * n + 0] = a.x;
        out[NUM_GRAPHS + 3 * n + 1] = a.y;
        out[NUM_GRAPHS + 3 * n + 2] = a.z;
        atomicAdd(&ebins[__ldg(&batch[n])], a.w);   // sorted batch: ~1 bin per block
    }
    __syncthreads();
    if (t < NUM_GRAPHS) {
        float v = ebins[t];
        if (v != 0.f) atomicAdd(&out[t], v);
    }
}

extern "C" void kernel_launch(void* const* d_in, const int* in_sizes, int n_in,
                              void* d_out, int out_size) {
    const float* pos   = (const float*)d_in[0];
    const int*   ei    = (const int*)d_in[1];
    const int*   batch = (const int*)d_in[2];
    float* out = (float*)d_out;

    int N = in_sizes[0] / 3;
    int E = in_sizes[1] / 2;

    {
        int threads = 128;
        int blocks  = (N + threads - 1) / threads;
        prep_kernel<<<blocks, threads>>>(pos, out, N);
    }
    if ((E & 3) == 0) {
        int Q = E >> 2;
        int threads = 64;
        int blocks  = (Q + threads - 1) / threads;
        edge_vec_kernel<<<blocks, threads>>>((const int4*)ei, (const int4*)(ei + E), Q);
    } else {
        int threads = 128;
        int blocks  = (E + threads - 1) / threads;
        edge_scalar_kernel<<<blocks, threads>>>(ei, E);
    }
    {
        int threads = 128;
        int blocks  = (N + threads - 1) / threads;
        finalize_kernel<<<blocks, threads>>>(out, batch, N);
    }
}

// round 17
// speedup vs baseline: 1.5257x; 1.5257x over previous
#include <cuda_runtime.h>
#include <cstdint>

// Harmonic lattice potential — FINAL (= R13, measured best 59.87us).
//   inputs: pos (N,3) f32, edge_index (2,E) int32, batch (N,) i32 (sorted)
//   output: energy (64,) f32 ++ forces (N,3) f32
//
// R16 note: R15 ran this exact binary at 94.8us with the prep canary kernel
// (16 regs, unchanged) simultaneously 25-35% slower than its history and
// HBM tput down proportionally -> degraded/throttled hold, not a code
// effect. Resubmitting unchanged for a clean measurement.
//
// Design (validated over 14 rounds):
//   - prep: pack pos->float4 + zero accumulators + energy slots (one plain
//     kernel; launch-ramp bound — slimming/splitting/overlap regressed:
//     R5, R14).
//   - edge: exact-fit grid, 4 edges/thread, int4 index loads, float4 pos
//     gathers, red.global.add.v4.f32 (force.xyz + energy in .w), rsqrt
//     math, 64-thread CTAs. At its L1tex random-wavefront floor
//     (~4.1 wf/edge). Grid-stride (R2/R7/R8), 8 edges/thread (R6),
//     PDL (R4), fusion (R7/R8) all regressed.
//   - finalize: coalesced force writes + smem energy binning by sorted
//     batch, 128t.

#define R0F 1.0f
#define NUM_GRAPHS 64
#define MAXN 131072

__device__ float4 g_acc[MAXN];    // force.xyz + energy.w accumulator
__device__ float4 g_pos4[MAXN];   // packed positions

__device__ __forceinline__ void red_add_v4(float4* addr, float a, float b, float c, float d) {
    asm volatile("red.global.add.v4.f32 [%0], {%1, %2, %3, %4};"
                 :: "l"(addr), "f"(a), "f"(b), "f"(c), "f"(d));
}

__global__ void prep_kernel(const float* __restrict__ pos, float* __restrict__ out, int N) {
    int t = blockIdx.x * blockDim.x + threadIdx.x;
    if (t < N) {
        g_acc[t]  = make_float4(0.f, 0.f, 0.f, 0.f);
        g_pos4[t] = make_float4(__ldg(&pos[3 * t]), __ldg(&pos[3 * t + 1]),
                                __ldg(&pos[3 * t + 2]), 0.f);
    }
    if (t < NUM_GRAPHS) out[t] = 0.f;   // zero energy slots (d_out poisoned)
}

// Vector path: E % 4 == 0. One quad (4 edges) per thread, exact grid, 64t CTAs.
__global__ void __launch_bounds__(64)
edge_vec_kernel(const int4* __restrict__ ia, const int4* __restrict__ ja, int Q) {
    int q = blockIdx.x * blockDim.x + threadIdx.x;
    if (q >= Q) return;

    int4 iv = __ldg(&ia[q]);
    int4 jv = __ldg(&ja[q]);
    int is[4] = {iv.x, iv.y, iv.z, iv.w};
    int js[4] = {jv.x, jv.y, jv.z, jv.w};

    float4 pi[4], pj[4];
#pragma unroll
    for (int k = 0; k < 4; k++) {
        pi[k] = __ldg(&g_pos4[is[k]]);
        pj[k] = __ldg(&g_pos4[js[k]]);
    }

#pragma unroll
    for (int k = 0; k < 4; k++) {
        float dx = pi[k].x - pj[k].x;
        float dy = pi[k].y - pj[k].y;
        float dz = pi[k].z - pj[k].z;
        float dd = fmaf(dx, dx, fmaf(dy, dy, dz * dz));
        float rinv = rsqrtf(fmaxf(dd, 1e-40f));
        float d = dd * rinv;                  // = sqrt(dd); 0 when dd==0
        float delta = d - R0F;                // K = 1
        float e = 0.5f * delta * delta;
        float s = delta * rinv;               // dx==0 when dd==0 -> force 0
        float fx = s * dx, fy = s * dy, fz = s * dz;

        red_add_v4(&g_acc[is[k]], -fx, -fy, -fz, e);
        red_add_v4(&g_acc[js[k]],  fx,  fy,  fz, 0.f);
    }
}

// Scalar fallback (E % 4 != 0 — not expected for this dataset).
__global__ void edge_scalar_kernel(const int* __restrict__ ei, int E) {
    int e = blockIdx.x * blockDim.x + threadIdx.x;
    if (e >= E) return;
    int i = __ldg(&ei[e]);
    int j = __ldg(&ei[E + e]);
    float4 pi = __ldg(&g_pos4[i]);
    float4 pj = __ldg(&g_pos4[j]);
    float dx = pi.x - pj.x, dy = pi.y - pj.y, dz = pi.z - pj.z;
    float dd = fmaf(dx, dx, fmaf(dy, dy, dz * dz));
    float rinv = rsqrtf(fmaxf(dd, 1e-40f));
    float d = dd * rinv;
    float delta = d - R0F;
    float e2 = 0.5f * delta * delta;
    float s = delta * rinv;
    float fx = s * dx, fy = s * dy, fz = s * dz;
    red_add_v4(&g_acc[i], -fx, -fy, -fz, e2);
    red_add_v4(&g_acc[j],  fx,  fy,  fz, 0.f);
}

__global__ void finalize_kernel(float* __restrict__ out,
                                const int* __restrict__ batch, int N) {
    __shared__ float ebins[NUM_GRAPHS];
    int t = threadIdx.x;
    if (t < NUM_GRAPHS) ebins[t] = 0.f;
    __syncthreads();

    int n = blockIdx.x * blockDim.x + t;
    if (n < N) {
        float4 a = g_acc[n];
        out[NUM_GRAPHS + 3 * n + 0] = a.x;
        out[NUM_GRAPHS + 3 * n + 1] = a.y;
        out[NUM_GRAPHS + 3 * n + 2] = a.z;
        atomicAdd(&ebins[__ldg(&batch[n])], a.w);   // sorted batch: ~1 bin per block
    }
    __syncthreads();
    if (t < NUM_GRAPHS) {
        float v = ebins[t];
        if (v != 0.f) atomicAdd(&out[t], v);
    }
}

extern "C" void kernel_launch(void* const* d_in, const int* in_sizes, int n_in,
                              void* d_out, int out_size) {
    const float* pos   = (const float*)d_in[0];
    const int*   ei    = (const int*)d_in[1];
    const int*   batch = (const int*)d_in[2];
    float* out = (float*)d_out;

    int N = in_sizes[0] / 3;
    int E = in_sizes[1] / 2;

    {
        int threads = 128;
        int blocks  = (N + threads - 1) / threads;
        prep_kernel<<<blocks, threads>>>(pos, out, N);
    }
    if ((E & 3) == 0) {
        int Q = E >> 2;
        int threads = 64;
        int blocks  = (Q + threads - 1) / threads;
        edge_vec_kernel<<<blocks, threads>>>((const int4*)ei, (const int4*)(ei + E), Q);
    } else {
        int threads = 128;
        int blocks  = (E + threads - 1) / threads;
        edge_scalar_kernel<<<blocks, threads>>>(ei, E);
    }
    {
        int threads = 128;
        int blocks  = (N + threads - 1) / threads;
        finalize_kernel<<<blocks, threads>>>(out, batch, N);
    }
}